// round 8
// baseline (speedup 1.0000x reference)
#include <cuda_runtime.h>
#include <cuda_bf16.h>
#include <cuda_fp16.h>
#include <cstdint>

#define TOK    32768
#define CDIM   256
#define KCODE  8192
#define BM     128
#define NC     64                 // codes per chunk
#define NCHUNK (KCODE / NC)       // 128
#define TAU    0.08f

// ---------------- scratch (device globals) ---------------------------------------
__device__ __half g_ch[KCODE * CDIM];   // negated codebook, fp16
__device__ float  g_cn[KCODE];          // 0.5 * ||e||^2 (fp64-accurate)
__device__ int    g_ind[TOK];
__device__ int    g_rlist[TOK];
__device__ int    g_nrescue;

// ---------------- helpers --------------------------------------------------------
__device__ __forceinline__ uint32_t smem_u32(const void* p) {
    uint32_t a;
    asm("{ .reg .u64 t; cvta.to.shared.u64 t, %1; cvt.u32.u64 %0, t; }" : "=r"(a) : "l"(p));
    return a;
}
__device__ __forceinline__ void cp16(uint32_t dst, const void* src) {
    asm volatile("cp.async.cg.shared.global [%0], [%1], 16;" :: "r"(dst), "l"(src) : "memory");
}
#define CP_COMMIT() asm volatile("cp.async.commit_group;" ::: "memory")
#define CP_WAIT1()  asm volatile("cp.async.wait_group 1;" ::: "memory")

__device__ __forceinline__ void ldsm4(uint32_t addr, uint32_t& r0, uint32_t& r1,
                                      uint32_t& r2, uint32_t& r3)
{
    asm volatile("ldmatrix.sync.aligned.m8n8.x4.shared.b16 {%0,%1,%2,%3}, [%4];"
                 : "=r"(r0), "=r"(r1), "=r"(r2), "=r"(r3) : "r"(addr));
}
__device__ __forceinline__ void mma16816(float* c, const uint32_t* a,
                                         uint32_t b0, uint32_t b1)
{
    asm volatile("mma.sync.aligned.m16n8k16.row.col.f32.f16.f16.f32 "
                 "{%0,%1,%2,%3}, {%4,%5,%6,%7}, {%8,%9}, {%0,%1,%2,%3};"
                 : "+f"(c[0]), "+f"(c[1]), "+f"(c[2]), "+f"(c[3])
                 : "r"(a[0]), "r"(a[1]), "r"(a[2]), "r"(a[3]), "r"(b0), "r"(b1));
}

// smem layout (bytes):
//   A_H : 128 rows x 264 fp16 (pitch 528B) = 67584 @ 0
//   A_L : 67584                            @ 67584
//   B   : 2 bufs x (64 x 528B = 33792 data + 256B cn) = 34048 each @ 135168
#define A_L_OFF   67584u
#define B_OFF    135168u
#define B_BUF     34048u
#define CN_IN_B   33792u
#define SMEM_SZ  203264

// ---------------- kernel 1: NCHW -> [T,C] transpose ------------------------------
__global__ void k_transpose(const float* __restrict__ in, float* __restrict__ data)
{
    __shared__ float tile[32][33];
    const int c0 = blockIdx.x * 32, h = blockIdx.y, n = blockIdx.z;
    {
        const int wx = threadIdx.x & 31, cy = threadIdx.x >> 5;
        #pragma unroll
        for (int i = 0; i < 4; i++) {
            const int c = cy + i * 8;
            tile[c][wx] = in[(((size_t)n * CDIM + c0 + c) * 32 + h) * 32 + wx];
        }
    }
    __syncthreads();
    {
        const int c = threadIdx.x & 31, wq = threadIdx.x >> 5;
        #pragma unroll
        for (int i = 0; i < 4; i++) {
            const int w = wq + i * 8;
            data[(size_t)(n * 1024 + h * 32 + w) * CDIM + c0 + c] = tile[c][w];
        }
    }
}

// ---------------- kernel 2: codebook prep ----------------------------------------
__global__ void k_codeprep(const float* __restrict__ cb)
{
    if (blockIdx.x == 0 && threadIdx.x == 0) g_nrescue = 0;
    const int warp = threadIdx.x >> 5, lane = threadIdx.x & 31;
    const int code = blockIdx.x * 8 + warp;
    const float* row = cb + (size_t)code * CDIM;
    double s = 0.0;
    #pragma unroll
    for (int i = 0; i < 8; i++) {
        const int c = lane + i * 32;
        const float e = row[c];
        s += (double)e * (double)e;
        g_ch[(size_t)code * CDIM + c] = __float2half_rn(-e);
    }
    #pragma unroll
    for (int o = 16; o > 0; o >>= 1) s += __shfl_xor_sync(0xffffffffu, s, o);
    if (lane == 0) g_cn[code] = (float)(0.5 * s);
}

// ---------------- kernel 3: fp16 2-term split GEMM + argmin ----------------------
__global__ void __launch_bounds__(256, 1)
k_gemm_argmin(const float* __restrict__ data)
{
    extern __shared__ char smem[];
    const uint32_t sb = smem_u32(smem);
    const int tid = threadIdx.x, lane = tid & 31, warp = tid >> 5;
    const int blk = blockIdx.x;

    // ---- cp.async issue for B chunk c (64 codes x 512B data + 64 cn floats) ----
    const int brow = tid >> 2, bs0 = tid & 3;
    auto cp_chunk = [&](int c) {
        const __half* src = g_ch + ((size_t)c * NC + brow) * CDIM + bs0 * 8;
        uint32_t dst = sb + B_OFF + (uint32_t)(c & 1) * B_BUF
                     + (uint32_t)(brow * 528 + bs0 * 16);
        #pragma unroll
        for (int i = 0; i < 8; i++) cp16(dst + i * 64, src + i * 32);
        if (tid < 16)
            cp16(sb + B_OFF + (uint32_t)(c & 1) * B_BUF + CN_IN_B + tid * 16,
                 (const char*)(g_cn + c * NC) + tid * 16);
    };

    cp_chunk(0); CP_COMMIT();
    cp_chunk(1); CP_COMMIT();

    // ---- A tile: fp32 -> fp16 hi/lo into smem (pitch 264 fp16), overlaps cp ----
    {
        const float4* src = (const float4*)(data + (size_t)blk * BM * CDIM);
        #pragma unroll
        for (int i = 0; i < 32; i++) {
            const int u = tid + i * 256;
            const int row = u >> 6, c4 = u & 63;
            const float4 v = src[u];
            union { __half h[4]; uint2 q; } ph, pl;
            const float f[4] = {v.x, v.y, v.z, v.w};
            #pragma unroll
            for (int j = 0; j < 4; j++) {
                const __half hb = __float2half_rn(f[j]);
                ph.h[j] = hb;
                pl.h[j] = __float2half_rn(f[j] - __half2float(hb));
            }
            const uint32_t off = (uint32_t)(row * 528 + c4 * 8);
            *(uint2*)(smem + off)           = ph.q;
            *(uint2*)(smem + A_L_OFF + off) = pl.q;
        }
    }

    // ldmatrix per-thread bases
    const int a_row = warp * 16 + ((lane >> 3) & 1) * 8 + (lane & 7);
    const int a_c8  = (lane >> 4) * 8;
    const uint32_t aH_base = sb + (uint32_t)(a_row * 528 + a_c8 * 2);
    const uint32_t aL_base = aH_base + A_L_OFF;
    const int b_row = (lane >> 4) * 8 + (lane & 7);
    const int b_c8  = ((lane >> 3) & 1) * 8;
    const uint32_t bT_rel = (uint32_t)(b_row * 528 + b_c8 * 2);

    float v1[2] = {3.4e38f, 3.4e38f};
    float v2[2] = {3.4e38f, 3.4e38f};
    int   i1[2] = {0, 0};

    for (int n = 0; n < NCHUNK; ++n) {
        CP_WAIT1();
        __syncthreads();                                   // buf n&1 fully written

        float acc[8][4];
        #pragma unroll
        for (int t = 0; t < 8; t++) { acc[t][0]=0.f; acc[t][1]=0.f; acc[t][2]=0.f; acc[t][3]=0.f; }

        const uint32_t bufb = sb + B_OFF + (uint32_t)(n & 1) * B_BUF;
        const uint32_t bB   = bufb + bT_rel;

        #pragma unroll 4
        for (int kk = 0; kk < 16; ++kk) {
            uint32_t ah[4], al[4];
            ldsm4(aH_base + kk * 32, ah[0], ah[1], ah[2], ah[3]);
            ldsm4(aL_base + kk * 32, al[0], al[1], al[2], al[3]);
            #pragma unroll
            for (int t2 = 0; t2 < 4; ++t2) {
                uint32_t b0, b1, b2, b3;
                ldsm4(bB + (uint32_t)(t2 * 8448 + kk * 32), b0, b1, b2, b3);
                mma16816(acc[2 * t2],     ah, b0, b1);     // xh * eh
                mma16816(acc[2 * t2 + 1], ah, b2, b3);
                mma16816(acc[2 * t2],     al, b0, b1);     // xl * eh
                mma16816(acc[2 * t2 + 1], al, b2, b3);
            }
        }

        {   // epilogue: score = acc + 0.5||e||^2 (streamed with B), track top-2
            const float* cns = (const float*)(smem + (bufb - sb) + CN_IN_B);
            #pragma unroll
            for (int t = 0; t < 8; ++t) {
                const int c0 = t * 8 + (lane & 3) * 2;
                const float2 c2 = *(const float2*)(cns + c0);
                const float sc[4] = { acc[t][0] + c2.x, acc[t][1] + c2.y,
                                      acc[t][2] + c2.x, acc[t][3] + c2.y };
                #pragma unroll
                for (int j = 0; j < 4; j++) {
                    const int h = j >> 1;
                    const float v = sc[j];
                    const int idx = n * NC + c0 + (j & 1);
                    if (v < v1[h]) { v2[h] = v1[h]; v1[h] = v; i1[h] = idx; }
                    else if (v < v2[h]) { v2[h] = v; }
                }
            }
        }

        __syncthreads();                                   // all warps done with buf
        if (n + 2 < NCHUNK) cp_chunk(n + 2);
        CP_COMMIT();                                       // (empty group near tail)
    }

    // final top-2 reduce across the 4 lanes sharing each row
    #pragma unroll
    for (int h = 0; h < 2; ++h) {
        float a1 = v1[h], a2 = v2[h]; int ai = i1[h];
        #pragma unroll
        for (int off = 1; off <= 2; off <<= 1) {
            const float o1 = __shfl_xor_sync(0xffffffffu, a1, off);
            const int   oi = __shfl_xor_sync(0xffffffffu, ai, off);
            const float o2 = __shfl_xor_sync(0xffffffffu, a2, off);
            if (o1 < a1 || (o1 == a1 && oi < ai)) {
                a2 = fminf(a1, o2); a1 = o1; ai = oi;
            } else {
                a2 = fminf(o1, a2);
            }
        }
        if ((lane & 3) == 0) {
            const int row = blk * BM + warp * 16 + h * 8 + (lane >> 2);
            g_ind[row] = ai;
            if (a2 - a1 < TAU) {
                const int p = atomicAdd(&g_nrescue, 1);
                if (p < TOK) g_rlist[p] = row;
            }
        }
    }
}

// ---------------- kernel 3.5: rescue near-ties (ref-emulated fp32) ---------------
__device__ __forceinline__ void nadd(float& s, float& c, float v)
{
    const float t = s + v;
    c += (fabsf(s) >= fabsf(v)) ? ((s - t) + v) : ((v - t) + s);
    s = t;
}

__global__ void __launch_bounds__(256) k_rescue(const float* __restrict__ data,
                                                const float* __restrict__ cb)
{
    __shared__ float xs[CDIM];
    __shared__ float bv[256];
    __shared__ int   bi[256];
    const int tid = threadIdx.x;
    int nr = g_nrescue; if (nr > TOK) nr = TOK;

    for (int it = blockIdx.x; it < nr; it += gridDim.x) {
        const int t = g_rlist[it];
        __syncthreads();
        xs[tid] = data[(size_t)t * CDIM + tid];
        __syncthreads();

        float sA = 0.f, cA = 0.f;
        #pragma unroll 8
        for (int i = 0; i < CDIM; i++) {
            const float p = __fmul_rn(xs[i], xs[i]);
            nadd(sA, cA, p);
        }
        const float A = sA + cA;

        float best = 3.4e38f; int bidx = 0x7fffffff;
        for (int j = 0; j < KCODE / 256; j++) {
            const int k = tid + j * 256;
            const float* e = cb + (size_t)k * CDIM;
            float sG = 0.f, cG = 0.f;
            #pragma unroll 8
            for (int i = 0; i < CDIM; i++) {
                const float p  = __fmul_rn(xs[i], e[i]);
                const float pe = __fmaf_rn(xs[i], e[i], -p);
                nadd(sG, cG, p);
                cG += pe;
            }
            const float G = sG + cG;
            const float B = __fmul_rn(2.0f, G);
            const float C = __fmul_rn(2.0f, g_cn[k]);
            const float d = __fadd_rn(__fsub_rn(A, B), C);
            if (d < best || (d == best && k < bidx)) { best = d; bidx = k; }
        }

        bv[tid] = best; bi[tid] = bidx;
        __syncthreads();
        for (int o = 128; o > 0; o >>= 1) {
            if (tid < o) {
                const float ov = bv[tid + o]; const int oi = bi[tid + o];
                if (ov < bv[tid] || (ov == bv[tid] && oi < bi[tid])) {
                    bv[tid] = ov; bi[tid] = oi;
                }
            }
            __syncthreads();
        }
        if (tid == 0) g_ind[t] = bi[0];
    }
}

// ---------------- kernel 4: gather -> quantize + quantize_detach -----------------
__global__ void k_gather(const float* __restrict__ cb, float* __restrict__ out)
{
    const int id  = blockIdx.x * 256 + threadIdx.x;
    const int row = id >> 6, c4 = id & 63;
    const int ind = g_ind[row];
    const float4 v = ((const float4*)cb)[(size_t)ind * 64 + c4];
    float4* o4 = (float4*)out;
    o4[(size_t)row * 64 + c4] = v;
    o4[(size_t)TOK * 64 + (size_t)row * 64 + c4] = v;
}

// ---------------- launcher --------------------------------------------------------
extern "C" void kernel_launch(void* const* d_in, const int* in_sizes, int n_in,
                              void* d_out, int out_size)
{
    const float* input = (const float*)d_in[0];   // [32,256,32,32] fp32
    const float* cb    = (const float*)d_in[1];   // [8192,256] fp32
    float* out  = (float*)d_out;                  // [quantize | detach | data]
    float* data = out + (size_t)2 * TOK * CDIM;

    cudaFuncSetAttribute(k_gemm_argmin, cudaFuncAttributeMaxDynamicSharedMemorySize, SMEM_SZ);

    k_transpose  <<<dim3(8, 32, 32), 256>>>(input, data);
    k_codeprep   <<<1024, 256>>>(cb);
    k_gemm_argmin<<<256, 256, SMEM_SZ>>>(data);
    k_rescue     <<<256, 256>>>(data, cb);
    k_gather     <<<8192, 256>>>(cb, out);
}